// round 1
// baseline (speedup 1.0000x reference)
#include <cuda_runtime.h>
#include <math.h>

// Problem constants: B=2, S=512, E=512, H=8, dk=64, nq=8, N_LAYERS=2
#define NTOK 1024          // B*S
#define SROW 513           // padded score row (bank-conflict avoidance)

// Scratch (device globals; no allocation allowed)
__device__ float g_A[3 * 64 * 512];      // folded Pin@W_head, rows r=stream*64 + h*8+q
__device__ float g_qp[NTOK * 192];       // angles per token
__device__ float g_z[3 * 16 * 512 * 64]; // qz/kz/vz: [stream][b*8+h][s][d]
__device__ float g_ho[NTOK * 512];       // attention output, head-concat layout

// ---------------------------------------------------------------------------
// Kernel 1: A[stream][h*8+q][e] = sum_d Pin[stream][q][d] * W[stream][h*64+d][e]
// ---------------------------------------------------------------------------
__global__ void k_computeA(const float* __restrict__ Wq, const float* __restrict__ Wk,
                           const float* __restrict__ Wv,
                           const float* __restrict__ Pq, const float* __restrict__ Pk,
                           const float* __restrict__ Pv) {
    int idx = blockIdx.x * blockDim.x + threadIdx.x;
    if (idx >= 3 * 64 * 512) return;
    int stream = idx / (64 * 512);
    int rem = idx - stream * (64 * 512);
    int r = rem >> 9;
    int e = rem & 511;
    int h = r >> 3, q = r & 7;
    const float* W = (stream == 0) ? Wq : ((stream == 1) ? Wk : Wv);
    const float* P = (stream == 0) ? Pq : ((stream == 1) ? Pk : Pv);
    float acc = 0.f;
#pragma unroll
    for (int d = 0; d < 64; ++d)
        acc = fmaf(P[q * 64 + d], W[(h * 64 + d) * 512 + e], acc);
    g_A[idx] = acc;
}

// ---------------------------------------------------------------------------
// Generic tiled SGEMM: C(MxN) = A(MxK) @ B(NxK)^T, row-major, all dims
// multiples of tile sizes. BM=BN=64, BK=32, 256 threads, 4x4 microtile.
// ---------------------------------------------------------------------------
__global__ __launch_bounds__(256) void k_gemm_abt(const float* __restrict__ A,
                                                  const float* __restrict__ B,
                                                  float* __restrict__ C,
                                                  int N, int K) {
    __shared__ float As[32][64];  // [k][m]
    __shared__ float Bs[32][64];  // [k][n]
    int bm = blockIdx.y * 64, bn = blockIdx.x * 64;
    int tid = threadIdx.x;
    int tx = tid & 15, ty = tid >> 4;
    float acc[4][4] = {};

    for (int kk = 0; kk < K; kk += 32) {
#pragma unroll
        for (int i = 0; i < 2; ++i) {
            int t = tid + i * 256;            // 0..511
            int row = t >> 3;                 // 0..63
            int c4 = (t & 7) * 4;             // 0..28
            float4 va = *(const float4*)(A + (size_t)(bm + row) * K + kk + c4);
            As[c4 + 0][row] = va.x; As[c4 + 1][row] = va.y;
            As[c4 + 2][row] = va.z; As[c4 + 3][row] = va.w;
            float4 vb = *(const float4*)(B + (size_t)(bn + row) * K + kk + c4);
            Bs[c4 + 0][row] = vb.x; Bs[c4 + 1][row] = vb.y;
            Bs[c4 + 2][row] = vb.z; Bs[c4 + 3][row] = vb.w;
        }
        __syncthreads();
#pragma unroll 8
        for (int k = 0; k < 32; ++k) {
            float4 a = *(const float4*)&As[k][ty * 4];
            float4 b = *(const float4*)&Bs[k][tx * 4];
            float av[4] = {a.x, a.y, a.z, a.w};
            float bv[4] = {b.x, b.y, b.z, b.w};
#pragma unroll
            for (int i = 0; i < 4; ++i)
#pragma unroll
                for (int j = 0; j < 4; ++j)
                    acc[i][j] = fmaf(av[i], bv[j], acc[i][j]);
        }
        __syncthreads();
    }
#pragma unroll
    for (int i = 0; i < 4; ++i) {
        float4 o = make_float4(acc[i][0], acc[i][1], acc[i][2], acc[i][3]);
        *(float4*)(C + (size_t)(bm + ty * 4 + i) * N + bn + tx * 4) = o;
    }
}

// ---------------------------------------------------------------------------
// Kernel 3: analytic circuit + Pout projection.
// z[w] = prod_{j<=w} cos(qp_j) * cos(theta_j + theta_{8+j});
// qz[d] = sum_w z[w]*Pout[d][w]
// ---------------------------------------------------------------------------
__global__ void k_zpout(const float* __restrict__ Pout_q, const float* __restrict__ Pout_k,
                        const float* __restrict__ Pout_v, const float* __restrict__ theta) {
    int n = blockIdx.x;          // token
    int t = threadIdx.x;         // 0..191
    int stream = t / 64;
    int lane = t - stream * 64;  // = h*8 + w
    __shared__ float cz[3][64];
    int w0 = lane & 7;
    float ct = cosf(theta[w0] + theta[8 + w0]);
    cz[stream][lane] = cosf(g_qp[n * 192 + t]) * ct;
    __syncthreads();

    const float* Pout = (stream == 0) ? Pout_q : ((stream == 1) ? Pout_k : Pout_v);
    int b = n >> 9, s = n & 511;
    int d = lane;
#pragma unroll
    for (int h = 0; h < 8; ++h) {
        float z = 1.f, acc = 0.f;
#pragma unroll
        for (int w = 0; w < 8; ++w) {
            z *= cz[stream][h * 8 + w];
            acc = fmaf(z, Pout[d * 8 + w], acc);
        }
        g_z[(((size_t)stream * 16 + (b * 8 + h)) * 512 + s) * 64 + d] = acc;
    }
}

// ---------------------------------------------------------------------------
// Kernel 4: fused attention per (bh, 64-q-row tile). Scores in smem (2-pass),
// softmax (4 threads/row), PV. Writes ho in concat-head layout.
// ---------------------------------------------------------------------------
__global__ __launch_bounds__(256) void k_attn() {
    extern __shared__ float sm[];
    float* scores = sm;                       // 64 * SROW
    float* Qst = sm + 64 * SROW;              // [d][r] 64*64
    float* KVs = Qst + 64 * 64;               // 64*64
    float* linv = KVs + 64 * 64;              // 64

    int bh = blockIdx.y;
    int q0 = blockIdx.x * 64;
    const float* Qz = g_z + (size_t)bh * 512 * 64;
    const float* Kz = g_z + (size_t)(16 + bh) * 512 * 64;
    const float* Vz = g_z + (size_t)(32 + bh) * 512 * 64;
    int tid = threadIdx.x;
    int tx = tid & 15, ty = tid >> 4;

    // Load Q tile transposed: Qst[d][r]
#pragma unroll
    for (int i = 0; i < 4; ++i) {
        int t = tid + i * 256;
        int row = t >> 4;
        int c4 = (t & 15) * 4;
        float4 v = *(const float4*)(Qz + (size_t)(q0 + row) * 64 + c4);
        Qst[(c4 + 0) * 64 + row] = v.x; Qst[(c4 + 1) * 64 + row] = v.y;
        Qst[(c4 + 2) * 64 + row] = v.z; Qst[(c4 + 3) * 64 + row] = v.w;
    }

    // Phase 1: scores = Q @ K^T * 0.125
    for (int kt = 0; kt < 8; ++kt) {
#pragma unroll
        for (int i = 0; i < 4; ++i) {
            int t = tid + i * 256;
            int row = t >> 4;
            int c4 = (t & 15) * 4;
            float4 v = *(const float4*)(Kz + (size_t)(kt * 64 + row) * 64 + c4);
            KVs[(c4 + 0) * 64 + row] = v.x; KVs[(c4 + 1) * 64 + row] = v.y;
            KVs[(c4 + 2) * 64 + row] = v.z; KVs[(c4 + 3) * 64 + row] = v.w;
        }
        __syncthreads();
        float acc[4][4] = {};
#pragma unroll 8
        for (int d = 0; d < 64; ++d) {
            float4 a = *(const float4*)&Qst[d * 64 + ty * 4];
            float4 b = *(const float4*)&KVs[d * 64 + tx * 4];
            float av[4] = {a.x, a.y, a.z, a.w};
            float bv[4] = {b.x, b.y, b.z, b.w};
#pragma unroll
            for (int i = 0; i < 4; ++i)
#pragma unroll
                for (int j = 0; j < 4; ++j)
                    acc[i][j] = fmaf(av[i], bv[j], acc[i][j]);
        }
#pragma unroll
        for (int i = 0; i < 4; ++i) {
            float* srow = scores + (ty * 4 + i) * SROW + kt * 64 + tx * 4;
            srow[0] = acc[i][0] * 0.125f;
            srow[1] = acc[i][1] * 0.125f;
            srow[2] = acc[i][2] * 0.125f;
            srow[3] = acc[i][3] * 0.125f;
        }
        __syncthreads();
    }

    // Phase 2: softmax (4 threads per row)
    {
        int row = tid >> 2, sub = tid & 3;
        float m = -1e30f;
        for (int t = sub; t < 512; t += 4) m = fmaxf(m, scores[row * SROW + t]);
        m = fmaxf(m, __shfl_xor_sync(0xffffffffu, m, 1));
        m = fmaxf(m, __shfl_xor_sync(0xffffffffu, m, 2));
        float l = 0.f;
        for (int t = sub; t < 512; t += 4) {
            float p = __expf(scores[row * SROW + t] - m);
            scores[row * SROW + t] = p;
            l += p;
        }
        l += __shfl_xor_sync(0xffffffffu, l, 1);
        l += __shfl_xor_sync(0xffffffffu, l, 2);
        if (sub == 0) linv[row] = 1.f / l;
    }
    __syncthreads();

    // Phase 3: out = P @ V
    float acc[4][4] = {};
    for (int vt = 0; vt < 8; ++vt) {
#pragma unroll
        for (int i = 0; i < 4; ++i) {
            int t = tid + i * 256;
            int row = t >> 4;
            int c4 = (t & 15) * 4;
            *(float4*)&KVs[row * 64 + c4] = *(const float4*)(Vz + (size_t)(vt * 64 + row) * 64 + c4);
        }
        __syncthreads();
#pragma unroll 8
        for (int tt = 0; tt < 64; ++tt) {
            float4 b = *(const float4*)&KVs[tt * 64 + tx * 4];
            float bv[4] = {b.x, b.y, b.z, b.w};
#pragma unroll
            for (int i = 0; i < 4; ++i) {
                float p = scores[(ty * 4 + i) * SROW + vt * 64 + tt];
                acc[i][0] = fmaf(p, bv[0], acc[i][0]);
                acc[i][1] = fmaf(p, bv[1], acc[i][1]);
                acc[i][2] = fmaf(p, bv[2], acc[i][2]);
                acc[i][3] = fmaf(p, bv[3], acc[i][3]);
            }
        }
        __syncthreads();
    }

    int b = bh >> 3, h = bh & 7;
#pragma unroll
    for (int i = 0; i < 4; ++i) {
        int qr = q0 + ty * 4 + i;
        float li = linv[ty * 4 + i];
        float4 o = make_float4(acc[i][0] * li, acc[i][1] * li, acc[i][2] * li, acc[i][3] * li);
        *(float4*)(g_ho + (size_t)(b * 512 + qr) * 512 + h * 64 + tx * 4) = o;
    }
}

// ---------------------------------------------------------------------------
extern "C" void kernel_launch(void* const* d_in, const int* in_sizes, int n_in,
                              void* d_out, int out_size) {
    const float* x      = (const float*)d_in[0];
    const float* Wq     = (const float*)d_in[1];
    const float* Wk     = (const float*)d_in[2];
    const float* Wv     = (const float*)d_in[3];
    const float* Wo     = (const float*)d_in[4];
    const float* Pin_q  = (const float*)d_in[5];
    const float* Pin_k  = (const float*)d_in[6];
    const float* Pin_v  = (const float*)d_in[7];
    const float* Pout_q = (const float*)d_in[8];
    const float* Pout_k = (const float*)d_in[9];
    const float* Pout_v = (const float*)d_in[10];
    const float* theta  = (const float*)d_in[11];
    float* out = (float*)d_out;

    float *pA, *pqp, *pho;
    cudaGetSymbolAddress((void**)&pA, g_A);
    cudaGetSymbolAddress((void**)&pqp, g_qp);
    cudaGetSymbolAddress((void**)&pho, g_ho);

    // 1) fold Pin @ W_head
    k_computeA<<<(3 * 64 * 512 + 255) / 256, 256>>>(Wq, Wk, Wv, Pin_q, Pin_k, Pin_v);
    // 2) qp = x @ A^T  (M=1024, N=192, K=512)
    k_gemm_abt<<<dim3(3, 16), 256>>>(x, pA, pqp, 192, 512);
    // 3) analytic circuit + Pout -> qz/kz/vz
    k_zpout<<<1024, 192>>>(Pout_q, Pout_k, Pout_v, theta);
    // 4) fused attention
    int smem = (64 * SROW + 64 * 64 + 64 * 64 + 64) * (int)sizeof(float);
    cudaFuncSetAttribute(k_attn, cudaFuncAttributeMaxDynamicSharedMemorySize, smem);
    k_attn<<<dim3(8, 16), 256, smem>>>();
    // 5) out = ho @ Wo^T  (M=1024, N=512, K=512)
    k_gemm_abt<<<dim3(8, 16), 256>>>(pho, Wo, out, 512, 512);
}

// round 2
// speedup vs baseline: 2.0910x; 2.0910x over previous
#include <cuda_runtime.h>
#include <math.h>

#define NTOK 1024   // B*S = 2*512

// Scratch (device globals)
__device__ float g_A[3 * 64 * 512];       // folded Pin@W_head
__device__ float g_U[512 * 64];           // folded Wo@Pout_v
__device__ float g_qp_part[4 * NTOK * 192]; // split-K partials of x@A^T
__device__ float g_z[3 * 16 * 512 * 8];   // [stream][bh][s][8]; stream0 = zq' (M-folded)
__device__ float g_Y[NTOK * 64];          // attn output in rank-8 space, [n][h*8+q]

// ---------------------------------------------------------------------------
// A[stream][h*8+q][e] = sum_d Pin[stream][q][d] * W[stream][h*64+d][e]
// grid 48 x 256 (idx = stream*4096 + h*512 + e)
// ---------------------------------------------------------------------------
__global__ void k_foldA(const float* __restrict__ Wq, const float* __restrict__ Wk,
                        const float* __restrict__ Wv,
                        const float* __restrict__ Pq, const float* __restrict__ Pk,
                        const float* __restrict__ Pv) {
    __shared__ float sP[512];
    int idx = blockIdx.x * 256 + threadIdx.x;
    int stream = idx >> 12;
    int rem = idx & 4095;
    int h = rem >> 9;
    int e = rem & 511;
    const float* W = (stream == 0) ? Wq : ((stream == 1) ? Wk : Wv);
    const float* P = (stream == 0) ? Pq : ((stream == 1) ? Pk : Pv);
    sP[threadIdx.x] = P[threadIdx.x];
    sP[threadIdx.x + 256] = P[threadIdx.x + 256];
    __syncthreads();
    float acc[8] = {};
#pragma unroll
    for (int d = 0; d < 64; ++d) {
        float w = W[(h * 64 + d) * 512 + e];
#pragma unroll
        for (int q = 0; q < 8; ++q)
            acc[q] = fmaf(sP[q * 64 + d], w, acc[q]);
    }
#pragma unroll
    for (int q = 0; q < 8; ++q)
        g_A[(stream * 64 + h * 8 + q) * 512 + e] = acc[q];
}

// ---------------------------------------------------------------------------
// U[e][h*8+q] = sum_d Wo[e][h*64+d] * Pout_v[d][q]   grid 16 x 256
// ---------------------------------------------------------------------------
__global__ void k_foldU(const float* __restrict__ Wo, const float* __restrict__ Pv) {
    __shared__ float sP[512];
    int idx = blockIdx.x * 256 + threadIdx.x;
    sP[threadIdx.x] = Pv[threadIdx.x];
    sP[threadIdx.x + 256] = Pv[threadIdx.x + 256];
    __syncthreads();
    int e = idx >> 3, h = idx & 7;
    float acc[8] = {};
#pragma unroll
    for (int d = 0; d < 64; ++d) {
        float w = Wo[e * 512 + h * 64 + d];
#pragma unroll
        for (int q = 0; q < 8; ++q)
            acc[q] = fmaf(w, sP[d * 8 + q], acc[q]);
    }
#pragma unroll
    for (int q = 0; q < 8; ++q)
        g_U[e * 64 + h * 8 + q] = acc[q];
}

// ---------------------------------------------------------------------------
// Split-K GEMM: qp_part[z] = x[:, z*128:(z+1)*128] @ A[:, same]^T
// grid (3, 16, 4), 256 threads, 64x64 tile, BK=32, 4x4 microtile
// ---------------------------------------------------------------------------
__global__ __launch_bounds__(256) void k_gemm_qp(const float* __restrict__ A) {
    const float* B = g_A;
    __shared__ float As[32][64];
    __shared__ float Bs[32][64];
    int bm = blockIdx.y * 64, bn = blockIdx.x * 64;
    int z = blockIdx.z;
    float* C = g_qp_part + z * (NTOK * 192);
    int tid = threadIdx.x, tx = tid & 15, ty = tid >> 4;
    float acc[4][4] = {};
    for (int kk = z * 128; kk < z * 128 + 128; kk += 32) {
#pragma unroll
        for (int i = 0; i < 2; ++i) {
            int t = tid + i * 256;
            int row = t >> 3;
            int c4 = (t & 7) * 4;
            float4 va = *(const float4*)(A + (size_t)(bm + row) * 512 + kk + c4);
            As[c4 + 0][row] = va.x; As[c4 + 1][row] = va.y;
            As[c4 + 2][row] = va.z; As[c4 + 3][row] = va.w;
            float4 vb = *(const float4*)(B + (size_t)(bn + row) * 512 + kk + c4);
            Bs[c4 + 0][row] = vb.x; Bs[c4 + 1][row] = vb.y;
            Bs[c4 + 2][row] = vb.z; Bs[c4 + 3][row] = vb.w;
        }
        __syncthreads();
#pragma unroll 8
        for (int k = 0; k < 32; ++k) {
            float4 a = *(const float4*)&As[k][ty * 4];
            float4 b = *(const float4*)&Bs[k][tx * 4];
            float av[4] = {a.x, a.y, a.z, a.w};
            float bv[4] = {b.x, b.y, b.z, b.w};
#pragma unroll
            for (int i = 0; i < 4; ++i)
#pragma unroll
                for (int j = 0; j < 4; ++j)
                    acc[i][j] = fmaf(av[i], bv[j], acc[i][j]);
        }
        __syncthreads();
    }
#pragma unroll
    for (int i = 0; i < 4; ++i) {
        float4 o = make_float4(acc[i][0], acc[i][1], acc[i][2], acc[i][3]);
        *(float4*)(C + (size_t)(bm + ty * 4 + i) * 192 + bn + tx * 4) = o;
    }
}

// ---------------------------------------------------------------------------
// z kernel: sum split-K partials, analytic circuit (cos prefix products),
// apply M = Pout_q^T Pout_k / 8 to the q-stream. grid 64 x 384.
// ---------------------------------------------------------------------------
__global__ void k_z(const float* __restrict__ Pq, const float* __restrict__ Pk,
                    const float* __restrict__ theta) {
    __shared__ float sM[64];
    __shared__ float sct[8];
    int t = threadIdx.x;
    if (t < 64) {
        int i = t >> 3, j = t & 7;
        float acc = 0.f;
#pragma unroll
        for (int d = 0; d < 64; ++d)
            acc = fmaf(Pq[d * 8 + i], Pk[d * 8 + j], acc);
        sM[t] = acc * 0.125f;
    } else if (t < 72) {
        int w = t - 64;
        sct[w] = cosf(theta[w] + theta[8 + w]);
    }
    __syncthreads();
    int tok = t / 24, slot = t % 24;
    int stream = slot >> 3, h = slot & 7;
    int n = blockIdx.x * 16 + tok;
    int base = n * 192 + stream * 64 + h * 8;
    float z[8];
    {
        float p = 1.f;
#pragma unroll
        for (int w = 0; w < 8; ++w) {
            float a = g_qp_part[base + w] + g_qp_part[NTOK * 192 + base + w]
                    + g_qp_part[2 * NTOK * 192 + base + w] + g_qp_part[3 * NTOK * 192 + base + w];
            p *= cosf(a) * sct[w];
            z[w] = p;
        }
    }
    float y[8];
    if (stream == 0) {
#pragma unroll
        for (int j = 0; j < 8; ++j) {
            float acc = 0.f;
#pragma unroll
            for (int i = 0; i < 8; ++i)
                acc = fmaf(z[i], sM[i * 8 + j], acc);
            y[j] = acc;
        }
    } else {
#pragma unroll
        for (int j = 0; j < 8; ++j) y[j] = z[j];
    }
    int b = n >> 9, s = n & 511;
    float* dst = g_z + ((size_t)(stream * 16 + b * 8 + h) * 512 + s) * 8;
#pragma unroll
    for (int j = 0; j < 8; ++j) dst[j] = y[j];
}

// ---------------------------------------------------------------------------
// Rank-8 attention. grid (8 qtiles, 16 bh), 256 threads.
// Thread = (rowgroup of 2 rows, sub 0..7). Each sub handles keys sub::8.
// Two-pass softmax with score recompute (8-FMA dots), shfl reductions.
// ---------------------------------------------------------------------------
__global__ __launch_bounds__(256) void k_attn2() {
    __shared__ float s_zk[512 * 9];
    __shared__ float s_zv[512 * 9];
    int bh = blockIdx.y;
    int q0 = blockIdx.x * 64;
    const float* gzq = g_z + (size_t)bh * 512 * 8;
    const float* gzk = g_z + (size_t)(16 + bh) * 512 * 8;
    const float* gzv = g_z + (size_t)(32 + bh) * 512 * 8;
    int tid = threadIdx.x;

    for (int r = tid; r < 512; r += 256) {
        float4 a = ((const float4*)gzk)[r * 2], b = ((const float4*)gzk)[r * 2 + 1];
        float* d = s_zk + r * 9;
        d[0] = a.x; d[1] = a.y; d[2] = a.z; d[3] = a.w;
        d[4] = b.x; d[5] = b.y; d[6] = b.z; d[7] = b.w;
        float4 c = ((const float4*)gzv)[r * 2], e = ((const float4*)gzv)[r * 2 + 1];
        float* f = s_zv + r * 9;
        f[0] = c.x; f[1] = c.y; f[2] = c.z; f[3] = c.w;
        f[4] = e.x; f[5] = e.y; f[6] = e.z; f[7] = e.w;
    }
    __syncthreads();

    int rg = tid >> 3, sub = tid & 7;
    int r0 = q0 + rg * 2;
    float y0[8], y1[8];
    {
        float4 a = ((const float4*)gzq)[r0 * 2], b = ((const float4*)gzq)[r0 * 2 + 1];
        y0[0] = a.x; y0[1] = a.y; y0[2] = a.z; y0[3] = a.w;
        y0[4] = b.x; y0[5] = b.y; y0[6] = b.z; y0[7] = b.w;
        float4 c = ((const float4*)gzq)[(r0 + 1) * 2], e = ((const float4*)gzq)[(r0 + 1) * 2 + 1];
        y1[0] = c.x; y1[1] = c.y; y1[2] = c.z; y1[3] = c.w;
        y1[4] = e.x; y1[5] = e.y; y1[6] = e.z; y1[7] = e.w;
    }

    // Pass 1: row max
    float m0 = -1e30f, m1 = -1e30f;
    for (int it = 0; it < 64; ++it) {
        const float* kp = s_zk + (sub + it * 8) * 9;
        float s0 = y0[0] * kp[0], s1 = y1[0] * kp[0];
#pragma unroll
        for (int j = 1; j < 8; ++j) {
            s0 = fmaf(y0[j], kp[j], s0);
            s1 = fmaf(y1[j], kp[j], s1);
        }
        m0 = fmaxf(m0, s0);
        m1 = fmaxf(m1, s1);
    }
    m0 = fmaxf(m0, __shfl_xor_sync(0xffffffffu, m0, 1));
    m0 = fmaxf(m0, __shfl_xor_sync(0xffffffffu, m0, 2));
    m0 = fmaxf(m0, __shfl_xor_sync(0xffffffffu, m0, 4));
    m1 = fmaxf(m1, __shfl_xor_sync(0xffffffffu, m1, 1));
    m1 = fmaxf(m1, __shfl_xor_sync(0xffffffffu, m1, 2));
    m1 = fmaxf(m1, __shfl_xor_sync(0xffffffffu, m1, 4));

    // Pass 2: exp, sum, P@zv
    float l0 = 0.f, l1 = 0.f;
    float acc0[8] = {}, acc1[8] = {};
    for (int it = 0; it < 64; ++it) {
        int key = sub + it * 8;
        const float* kp = s_zk + key * 9;
        float s0 = y0[0] * kp[0], s1 = y1[0] * kp[0];
#pragma unroll
        for (int j = 1; j < 8; ++j) {
            s0 = fmaf(y0[j], kp[j], s0);
            s1 = fmaf(y1[j], kp[j], s1);
        }
        float p0 = __expf(s0 - m0);
        float p1 = __expf(s1 - m1);
        l0 += p0;
        l1 += p1;
        const float* vp = s_zv + key * 9;
#pragma unroll
        for (int j = 0; j < 8; ++j) {
            acc0[j] = fmaf(p0, vp[j], acc0[j]);
            acc1[j] = fmaf(p1, vp[j], acc1[j]);
        }
    }
#pragma unroll
    for (int d = 1; d <= 4; d <<= 1) {
        l0 += __shfl_xor_sync(0xffffffffu, l0, d);
        l1 += __shfl_xor_sync(0xffffffffu, l1, d);
#pragma unroll
        for (int j = 0; j < 8; ++j) {
            acc0[j] += __shfl_xor_sync(0xffffffffu, acc0[j], d);
            acc1[j] += __shfl_xor_sync(0xffffffffu, acc1[j], d);
        }
    }
    if (sub == 0) {
        int b = bh >> 3, h = bh & 7;
        float inv0 = 1.f / l0, inv1 = 1.f / l1;
        int n0 = b * 512 + r0;
        float4* o = (float4*)(g_Y + (size_t)n0 * 64 + h * 8);
        o[0] = make_float4(acc0[0] * inv0, acc0[1] * inv0, acc0[2] * inv0, acc0[3] * inv0);
        o[1] = make_float4(acc0[4] * inv0, acc0[5] * inv0, acc0[6] * inv0, acc0[7] * inv0);
        float4* o2 = (float4*)(g_Y + (size_t)(n0 + 1) * 64 + h * 8);
        o2[0] = make_float4(acc1[0] * inv1, acc1[1] * inv1, acc1[2] * inv1, acc1[3] * inv1);
        o2[1] = make_float4(acc1[4] * inv1, acc1[5] * inv1, acc1[6] * inv1, acc1[7] * inv1);
    }
}

// ---------------------------------------------------------------------------
// Generic tiled SGEMM: C(MxN) = A(MxK) @ B(NxK)^T (final: Y @ U^T)
// ---------------------------------------------------------------------------
__global__ __launch_bounds__(256) void k_gemm_abt(const float* __restrict__ A,
                                                  const float* __restrict__ B,
                                                  float* __restrict__ C,
                                                  int N, int K) {
    __shared__ float As[32][64];
    __shared__ float Bs[32][64];
    int bm = blockIdx.y * 64, bn = blockIdx.x * 64;
    int tid = threadIdx.x;
    int tx = tid & 15, ty = tid >> 4;
    float acc[4][4] = {};
    for (int kk = 0; kk < K; kk += 32) {
#pragma unroll
        for (int i = 0; i < 2; ++i) {
            int t = tid + i * 256;
            int row = t >> 3;
            int c4 = (t & 7) * 4;
            float4 va = *(const float4*)(A + (size_t)(bm + row) * K + kk + c4);
            As[c4 + 0][row] = va.x; As[c4 + 1][row] = va.y;
            As[c4 + 2][row] = va.z; As[c4 + 3][row] = va.w;
            float4 vb = *(const float4*)(B + (size_t)(bn + row) * K + kk + c4);
            Bs[c4 + 0][row] = vb.x; Bs[c4 + 1][row] = vb.y;
            Bs[c4 + 2][row] = vb.z; Bs[c4 + 3][row] = vb.w;
        }
        __syncthreads();
#pragma unroll 8
        for (int k = 0; k < 32; ++k) {
            float4 a = *(const float4*)&As[k][ty * 4];
            float4 b = *(const float4*)&Bs[k][tx * 4];
            float av[4] = {a.x, a.y, a.z, a.w};
            float bv[4] = {b.x, b.y, b.z, b.w};
#pragma unroll
            for (int i = 0; i < 4; ++i)
#pragma unroll
                for (int j = 0; j < 4; ++j)
                    acc[i][j] = fmaf(av[i], bv[j], acc[i][j]);
        }
        __syncthreads();
    }
#pragma unroll
    for (int i = 0; i < 4; ++i) {
        float4 o = make_float4(acc[i][0], acc[i][1], acc[i][2], acc[i][3]);
        *(float4*)(C + (size_t)(bm + ty * 4 + i) * N + bn + tx * 4) = o;
    }
}

// ---------------------------------------------------------------------------
extern "C" void kernel_launch(void* const* d_in, const int* in_sizes, int n_in,
                              void* d_out, int out_size) {
    const float* x      = (const float*)d_in[0];
    const float* Wq     = (const float*)d_in[1];
    const float* Wk     = (const float*)d_in[2];
    const float* Wv     = (const float*)d_in[3];
    const float* Wo     = (const float*)d_in[4];
    const float* Pin_q  = (const float*)d_in[5];
    const float* Pin_k  = (const float*)d_in[6];
    const float* Pin_v  = (const float*)d_in[7];
    const float* Pout_q = (const float*)d_in[8];
    const float* Pout_k = (const float*)d_in[9];
    const float* Pout_v = (const float*)d_in[10];
    const float* theta  = (const float*)d_in[11];
    float* out = (float*)d_out;

    float *pY, *pU;
    cudaGetSymbolAddress((void**)&pY, g_Y);
    cudaGetSymbolAddress((void**)&pU, g_U);

    k_foldA<<<48, 256>>>(Wq, Wk, Wv, Pin_q, Pin_k, Pin_v);
    k_foldU<<<16, 256>>>(Wo, Pout_v);
    k_gemm_qp<<<dim3(3, 16, 4), 256>>>(x);
    k_z<<<64, 384>>>(Pout_q, Pout_k, theta);
    k_attn2<<<dim3(8, 16), 256>>>();
    k_gemm_abt<<<dim3(8, 16), 256>>>(pY, pU, out, 512, 64);
}

// round 3
// speedup vs baseline: 2.9490x; 1.4103x over previous
#include <cuda_runtime.h>
#include <math.h>

#define NTOK 1024   // B*S = 2*512

// Scratch (device globals)
__device__ float g_A[3 * 64 * 512];         // folded Pin@W_head
__device__ float g_U[512 * 64];             // folded Wo@Pout_v
__device__ float g_M[64];                   // Pout_q^T Pout_k / 8
__device__ float g_ct[8];                   // cos(theta_w + theta_{8+w})
__device__ float g_qp_part[4 * NTOK * 192]; // split-K partials of x@A^T
__device__ float g_z[3 * 16 * 512 * 8];     // [stream][bh][s][8]; stream0 folded with M
__device__ float g_Y[NTOK * 64];            // attn out in rank-8 space, [n][h*8+q]

// ---------------------------------------------------------------------------
// Fused fold kernel. Blocks 0..47: A. Blocks 48..63: U. Block 64: M + ct.
// ---------------------------------------------------------------------------
__global__ __launch_bounds__(256) void k_fold(
    const float* __restrict__ Wq, const float* __restrict__ Wk,
    const float* __restrict__ Wv, const float* __restrict__ Wo,
    const float* __restrict__ Pq, const float* __restrict__ Pk,
    const float* __restrict__ Pv, const float* __restrict__ Poq,
    const float* __restrict__ Pok, const float* __restrict__ Pov,
    const float* __restrict__ theta) {
    __shared__ float sP[512];
    int blk = blockIdx.x;
    int t = threadIdx.x;
    if (blk < 48) {
        // A[stream][h*8+q][e] = sum_d Pin[stream][q][d] * W[stream][h*64+d][e]
        int idx = blk * 256 + t;
        int stream = idx >> 12;
        int rem = idx & 4095;
        int h = rem >> 9;
        int e = rem & 511;
        const float* W = (stream == 0) ? Wq : ((stream == 1) ? Wk : Wv);
        const float* P = (stream == 0) ? Pq : ((stream == 1) ? Pk : Pv);
        sP[t] = P[t];
        sP[t + 256] = P[t + 256];
        __syncthreads();
        float acc[8] = {};
#pragma unroll
        for (int d = 0; d < 64; ++d) {
            float w = W[(h * 64 + d) * 512 + e];
#pragma unroll
            for (int q = 0; q < 8; ++q)
                acc[q] = fmaf(sP[q * 64 + d], w, acc[q]);
        }
#pragma unroll
        for (int q = 0; q < 8; ++q)
            g_A[(stream * 64 + h * 8 + q) * 512 + e] = acc[q];
    } else if (blk < 64) {
        // U[e][h*8+q] = sum_d Wo[e][h*64+d] * Pout_v[d][q]
        int idx = (blk - 48) * 256 + t;
        sP[t] = Pov[t];
        sP[t + 256] = Pov[t + 256];
        __syncthreads();
        int e = idx >> 3, h = idx & 7;
        float acc[8] = {};
#pragma unroll
        for (int d = 0; d < 64; ++d) {
            float w = Wo[e * 512 + h * 64 + d];
#pragma unroll
            for (int q = 0; q < 8; ++q)
                acc[q] = fmaf(w, sP[d * 8 + q], acc[q]);
        }
#pragma unroll
        for (int q = 0; q < 8; ++q)
            g_U[e * 64 + h * 8 + q] = acc[q];
    } else {
        if (t < 64) {
            int i = t >> 3, j = t & 7;
            float acc = 0.f;
#pragma unroll
            for (int d = 0; d < 64; ++d)
                acc = fmaf(Poq[d * 8 + i], Pok[d * 8 + j], acc);
            g_M[t] = acc * 0.125f;
        } else if (t < 72) {
            int w = t - 64;
            g_ct[w] = cosf(theta[w] + theta[8 + w]);
        }
    }
}

// ---------------------------------------------------------------------------
// Split-K GEMM: qp_part[z] = x[:, z*128:(z+1)*128] @ A[:, same]^T
// grid (3, 16, 4), 256 threads, 64x64 tile, BK=32, 4x4 microtile
// ---------------------------------------------------------------------------
__global__ __launch_bounds__(256) void k_gemm_qp(const float* __restrict__ A) {
    const float* B = g_A;
    __shared__ float As[32][64];
    __shared__ float Bs[32][64];
    int bm = blockIdx.y * 64, bn = blockIdx.x * 64;
    int z = blockIdx.z;
    float* C = g_qp_part + z * (NTOK * 192);
    int tid = threadIdx.x, tx = tid & 15, ty = tid >> 4;
    float acc[4][4] = {};
    for (int kk = z * 128; kk < z * 128 + 128; kk += 32) {
#pragma unroll
        for (int i = 0; i < 2; ++i) {
            int t = tid + i * 256;
            int row = t >> 3;
            int c4 = (t & 7) * 4;
            float4 va = *(const float4*)(A + (size_t)(bm + row) * 512 + kk + c4);
            As[c4 + 0][row] = va.x; As[c4 + 1][row] = va.y;
            As[c4 + 2][row] = va.z; As[c4 + 3][row] = va.w;
            float4 vb = *(const float4*)(B + (size_t)(bn + row) * 512 + kk + c4);
            Bs[c4 + 0][row] = vb.x; Bs[c4 + 1][row] = vb.y;
            Bs[c4 + 2][row] = vb.z; Bs[c4 + 3][row] = vb.w;
        }
        __syncthreads();
#pragma unroll 8
        for (int k = 0; k < 32; ++k) {
            float4 a = *(const float4*)&As[k][ty * 4];
            float4 b = *(const float4*)&Bs[k][tx * 4];
            float av[4] = {a.x, a.y, a.z, a.w};
            float bv[4] = {b.x, b.y, b.z, b.w};
#pragma unroll
            for (int i = 0; i < 4; ++i)
#pragma unroll
                for (int j = 0; j < 4; ++j)
                    acc[i][j] = fmaf(av[i], bv[j], acc[i][j]);
        }
        __syncthreads();
    }
#pragma unroll
    for (int i = 0; i < 4; ++i) {
        float4 o = make_float4(acc[i][0], acc[i][1], acc[i][2], acc[i][3]);
        *(float4*)(C + (size_t)(bm + ty * 4 + i) * 192 + bn + tx * 4) = o;
    }
}

// ---------------------------------------------------------------------------
// z kernel: sum split-K partials (float4, MLP=8), cos prefix products,
// apply M to q-stream. grid 192 x 128 (one thread per (token, stream, head)).
// ---------------------------------------------------------------------------
__global__ __launch_bounds__(128) void k_z() {
    __shared__ float sM[64];
    __shared__ float sct[8];
    int t = threadIdx.x;
    if (t < 64) sM[t] = g_M[t];
    else if (t < 72) sct[t - 64] = g_ct[t - 64];
    __syncthreads();

    int idx = blockIdx.x * 128 + t;   // 0..24575
    int n = idx / 24;
    int slot = idx - n * 24;
    int stream = slot >> 3;
    int h = slot & 7;
    int base = n * 192 + stream * 64 + h * 8;

    // batch all 8 float4 loads (independent)
    float4 a0 = *(const float4*)(g_qp_part + base);
    float4 a1 = *(const float4*)(g_qp_part + base + 4);
    float4 b0 = *(const float4*)(g_qp_part + NTOK * 192 + base);
    float4 b1 = *(const float4*)(g_qp_part + NTOK * 192 + base + 4);
    float4 c0 = *(const float4*)(g_qp_part + 2 * NTOK * 192 + base);
    float4 c1 = *(const float4*)(g_qp_part + 2 * NTOK * 192 + base + 4);
    float4 d0 = *(const float4*)(g_qp_part + 3 * NTOK * 192 + base);
    float4 d1 = *(const float4*)(g_qp_part + 3 * NTOK * 192 + base + 4);
    float ang[8];
    ang[0] = a0.x + b0.x + c0.x + d0.x;
    ang[1] = a0.y + b0.y + c0.y + d0.y;
    ang[2] = a0.z + b0.z + c0.z + d0.z;
    ang[3] = a0.w + b0.w + c0.w + d0.w;
    ang[4] = a1.x + b1.x + c1.x + d1.x;
    ang[5] = a1.y + b1.y + c1.y + d1.y;
    ang[6] = a1.z + b1.z + c1.z + d1.z;
    ang[7] = a1.w + b1.w + c1.w + d1.w;

    float z[8];
    float p = 1.f;
#pragma unroll
    for (int w = 0; w < 8; ++w) {
        p *= cosf(ang[w]) * sct[w];
        z[w] = p;
    }
    float y[8];
    if (stream == 0) {
#pragma unroll
        for (int j = 0; j < 8; ++j) {
            float acc = 0.f;
#pragma unroll
            for (int i = 0; i < 8; ++i)
                acc = fmaf(z[i], sM[i * 8 + j], acc);
            y[j] = acc;
        }
    } else {
#pragma unroll
        for (int j = 0; j < 8; ++j) y[j] = z[j];
    }
    int b = n >> 9, s = n & 511;
    float* dst = g_z + ((size_t)(stream * 16 + b * 8 + h) * 512 + s) * 8;
    *(float4*)dst = make_float4(y[0], y[1], y[2], y[3]);
    *(float4*)(dst + 4) = make_float4(y[4], y[5], y[6], y[7]);
}

// ---------------------------------------------------------------------------
// Rank-8 attention, single pass (no max: |scores| provably < ~6, exp safe).
// grid (8 qtiles, 16 bh), 256 threads. Thread = (rowgroup of 4 rows, sub 0..15).
// ---------------------------------------------------------------------------
__global__ __launch_bounds__(256) void k_attn3() {
    __shared__ float s_zk[512 * 9];
    __shared__ float s_zv[512 * 9];
    int bh = blockIdx.y;
    int q0 = blockIdx.x * 64;
    const float* gzq = g_z + (size_t)bh * 4096;
    const float* gzk = g_z + (size_t)(16 + bh) * 4096;
    const float* gzv = g_z + (size_t)(32 + bh) * 4096;
    int tid = threadIdx.x;

    for (int r = tid; r < 512; r += 256) {
        float4 a = ((const float4*)gzk)[r * 2], b = ((const float4*)gzk)[r * 2 + 1];
        float* d = s_zk + r * 9;
        d[0] = a.x; d[1] = a.y; d[2] = a.z; d[3] = a.w;
        d[4] = b.x; d[5] = b.y; d[6] = b.z; d[7] = b.w;
        float4 c = ((const float4*)gzv)[r * 2], e = ((const float4*)gzv)[r * 2 + 1];
        float* f = s_zv + r * 9;
        f[0] = c.x; f[1] = c.y; f[2] = c.z; f[3] = c.w;
        f[4] = e.x; f[5] = e.y; f[6] = e.z; f[7] = e.w;
    }
    __syncthreads();

    int rg = tid >> 4, sub = tid & 15;
    int r0 = q0 + rg * 4;
    float y[4][8];
#pragma unroll
    for (int r = 0; r < 4; ++r) {
        float4 a = ((const float4*)gzq)[(r0 + r) * 2];
        float4 b = ((const float4*)gzq)[(r0 + r) * 2 + 1];
        y[r][0] = a.x; y[r][1] = a.y; y[r][2] = a.z; y[r][3] = a.w;
        y[r][4] = b.x; y[r][5] = b.y; y[r][6] = b.z; y[r][7] = b.w;
    }

    float l[4] = {};
    float acc[4][8] = {};
    for (int it = 0; it < 32; ++it) {
        int key = sub + it * 16;
        const float* kp = s_zk + key * 9;
        float kr[8];
#pragma unroll
        for (int j = 0; j < 8; ++j) kr[j] = kp[j];
        float p[4];
#pragma unroll
        for (int r = 0; r < 4; ++r) {
            float s = y[r][0] * kr[0];
#pragma unroll
            for (int j = 1; j < 8; ++j) s = fmaf(y[r][j], kr[j], s);
            p[r] = __expf(s);
            l[r] += p[r];
        }
        const float* vp = s_zv + key * 9;
        float vr[8];
#pragma unroll
        for (int j = 0; j < 8; ++j) vr[j] = vp[j];
#pragma unroll
        for (int r = 0; r < 4; ++r)
#pragma unroll
            for (int j = 0; j < 8; ++j)
                acc[r][j] = fmaf(p[r], vr[j], acc[r][j]);
    }

    // reduce over 16 subs (lanes 0..15 / 16..31 are independent groups)
#pragma unroll
    for (int d = 1; d <= 8; d <<= 1) {
#pragma unroll
        for (int r = 0; r < 4; ++r) {
            l[r] += __shfl_xor_sync(0xffffffffu, l[r], d);
#pragma unroll
            for (int j = 0; j < 8; ++j)
                acc[r][j] += __shfl_xor_sync(0xffffffffu, acc[r][j], d);
        }
    }
    if (sub == 0) {
        int b = bh >> 3, h = bh & 7;
#pragma unroll
        for (int r = 0; r < 4; ++r) {
            float inv = 1.f / l[r];
            int n0 = b * 512 + r0 + r;
            float4* o = (float4*)(g_Y + (size_t)n0 * 64 + h * 8);
            o[0] = make_float4(acc[r][0] * inv, acc[r][1] * inv, acc[r][2] * inv, acc[r][3] * inv);
            o[1] = make_float4(acc[r][4] * inv, acc[r][5] * inv, acc[r][6] * inv, acc[r][7] * inv);
        }
    }
}

// ---------------------------------------------------------------------------
// Final GEMM: out = Y(1024x64) @ U(512x64)^T
// ---------------------------------------------------------------------------
__global__ __launch_bounds__(256) void k_gemm_abt(const float* __restrict__ A,
                                                  const float* __restrict__ B,
                                                  float* __restrict__ C,
                                                  int N, int K) {
    __shared__ float As[32][64];
    __shared__ float Bs[32][64];
    int bm = blockIdx.y * 64, bn = blockIdx.x * 64;
    int tid = threadIdx.x;
    int tx = tid & 15, ty = tid >> 4;
    float acc[4][4] = {};
    for (int kk = 0; kk < K; kk += 32) {
#pragma unroll
        for (int i = 0; i < 2; ++i) {
            int t = tid + i * 256;
            int row = t >> 3;
            int c4 = (t & 7) * 4;
            float4 va = *(const float4*)(A + (size_t)(bm + row) * K + kk + c4);
            As[c4 + 0][row] = va.x; As[c4 + 1][row] = va.y;
            As[c4 + 2][row] = va.z; As[c4 + 3][row] = va.w;
            float4 vb = *(const float4*)(B + (size_t)(bn + row) * K + kk + c4);
            Bs[c4 + 0][row] = vb.x; Bs[c4 + 1][row] = vb.y;
            Bs[c4 + 2][row] = vb.z; Bs[c4 + 3][row] = vb.w;
        }
        __syncthreads();
#pragma unroll 8
        for (int k = 0; k < 32; ++k) {
            float4 a = *(const float4*)&As[k][ty * 4];
            float4 b = *(const float4*)&Bs[k][tx * 4];
            float av[4] = {a.x, a.y, a.z, a.w};
            float bv[4] = {b.x, b.y, b.z, b.w};
#pragma unroll
            for (int i = 0; i < 4; ++i)
#pragma unroll
                for (int j = 0; j < 4; ++j)
                    acc[i][j] = fmaf(av[i], bv[j], acc[i][j]);
        }
        __syncthreads();
    }
#pragma unroll
    for (int i = 0; i < 4; ++i) {
        float4 o = make_float4(acc[i][0], acc[i][1], acc[i][2], acc[i][3]);
        *(float4*)(C + (size_t)(bm + ty * 4 + i) * N + bn + tx * 4) = o;
    }
}

// ---------------------------------------------------------------------------
extern "C" void kernel_launch(void* const* d_in, const int* in_sizes, int n_in,
                              void* d_out, int out_size) {
    const float* x      = (const float*)d_in[0];
    const float* Wq     = (const float*)d_in[1];
    const float* Wk     = (const float*)d_in[2];
    const float* Wv     = (const float*)d_in[3];
    const float* Wo     = (const float*)d_in[4];
    const float* Pin_q  = (const float*)d_in[5];
    const float* Pin_k  = (const float*)d_in[6];
    const float* Pin_v  = (const float*)d_in[7];
    const float* Pout_q = (const float*)d_in[8];
    const float* Pout_k = (const float*)d_in[9];
    const float* Pout_v = (const float*)d_in[10];
    const float* theta  = (const float*)d_in[11];
    float* out = (float*)d_out;

    float *pY, *pU;
    cudaGetSymbolAddress((void**)&pY, g_Y);
    cudaGetSymbolAddress((void**)&pU, g_U);

    k_fold<<<65, 256>>>(Wq, Wk, Wv, Wo, Pin_q, Pin_k, Pin_v,
                        Pout_q, Pout_k, Pout_v, theta);
    k_gemm_qp<<<dim3(3, 16, 4), 256>>>(x);
    k_z<<<192, 128>>>();
    k_attn3<<<dim3(8, 16), 256>>>();
    k_gemm_abt<<<dim3(8, 16), 256>>>(pY, pU, out, 512, 64);
}